// round 8
// baseline (speedup 1.0000x reference)
#include <cuda_runtime.h>
#include <cuda_bf16.h>
#include <cstdint>

// ============================================================================
// spectralNNDeepshared2 — Round 7:
//   MLP chain: round-5 bf16 split mma.sync (measured best)
//   Output contraction: int8 IMMA (m16n8k32), exact 2-digit fixed point,
//     3 IMMA terms -> HALF the tensor instructions of bf16 3-term.
// ============================================================================

// ---------------- scratch ----------------
__device__ __nv_bfloat16 g_uThi[64 * 1024];
__device__ __nv_bfloat16 g_uTlo[64 * 1024];
__device__ __nv_bfloat16 g_W0hi[64 * 256 * 64];
__device__ __nv_bfloat16 g_W0lo[64 * 256 * 64];
__device__ __nv_bfloat16 g_Whi[3L * 64 * 256 * 256];
__device__ __nv_bfloat16 g_Wlo[3L * 64 * 256 * 256];
__device__ __nv_bfloat16 g_Wfhi[64 * 65 * 256];
__device__ __nv_bfloat16 g_Wflo[64 * 65 * 256];
__device__ __nv_bfloat16 g_actAhi[64L * 256 * 1024];
__device__ __nv_bfloat16 g_actAlo[64L * 256 * 1024];
__device__ __nv_bfloat16 g_actBhi[64L * 256 * 1024];
__device__ __nv_bfloat16 g_actBlo[64L * 256 * 1024];
__device__ __nv_bfloat16 g_Bhi[4160L * 1024];
__device__ __nv_bfloat16 g_Blo[4160L * 1024];
__device__ signed char g_Aq1[4096L * 4160];
__device__ signed char g_Aq0[4096L * 4160];
__device__ signed char g_Bq1[1024L * 4160];
__device__ signed char g_Bq0[1024L * 4160];
__device__ unsigned int g_maxbits;

__device__ __forceinline__ float sigmoidf_fast(float x) {
    return 1.0f / (1.0f + __expf(-x));
}
__device__ __forceinline__ uint32_t smem_u32(const void* p) {
    uint32_t a;
    asm("{ .reg .u64 t; cvta.to.shared.u64 t, %1; cvt.u32.u64 %0, t; }"
        : "=r"(a) : "l"(p));
    return a;
}

// ---------------- cp.async / ldmatrix / mma helpers ----------------
__device__ __forceinline__ void cp16(uint32_t dst, const void* src) {
    asm volatile("cp.async.cg.shared.global [%0], [%1], 16;\n"
                 :: "r"(dst), "l"(src));
}
__device__ __forceinline__ void cp16z(uint32_t dst, const void* src, bool valid) {
    int sz = valid ? 16 : 0;
    asm volatile("cp.async.cg.shared.global [%0], [%1], 16, %2;\n"
                 :: "r"(dst), "l"(src), "r"(sz));
}
#define CP_COMMIT() asm volatile("cp.async.commit_group;\n" ::: "memory")
#define CP_WAIT(n)  asm volatile("cp.async.wait_group %0;\n" :: "n"(n) : "memory")

__device__ __forceinline__ void ldsm_x4(uint32_t* r, uint32_t addr) {
    asm volatile("ldmatrix.sync.aligned.m8n8.x4.shared.b16 {%0,%1,%2,%3}, [%4];"
        : "=r"(r[0]), "=r"(r[1]), "=r"(r[2]), "=r"(r[3]) : "r"(addr));
}
__device__ __forceinline__ void ldsm_x4t(uint32_t* r, uint32_t addr) {
    asm volatile("ldmatrix.sync.aligned.m8n8.x4.trans.shared.b16 {%0,%1,%2,%3}, [%4];"
        : "=r"(r[0]), "=r"(r[1]), "=r"(r[2]), "=r"(r[3]) : "r"(addr));
}
__device__ __forceinline__ void mma_bf16(float* d, const uint32_t* a, const uint32_t* b) {
    asm volatile(
        "mma.sync.aligned.m16n8k16.row.col.f32.bf16.bf16.f32 "
        "{%0,%1,%2,%3}, {%4,%5,%6,%7}, {%8,%9}, {%0,%1,%2,%3};"
        : "+f"(d[0]), "+f"(d[1]), "+f"(d[2]), "+f"(d[3])
        : "r"(a[0]), "r"(a[1]), "r"(a[2]), "r"(a[3]), "r"(b[0]), "r"(b[1]));
}
__device__ __forceinline__ void mma_s8(int* d, const uint32_t* a, uint32_t b0, uint32_t b1) {
    asm volatile(
        "mma.sync.aligned.m16n8k32.row.col.s32.s8.s8.s32 "
        "{%0,%1,%2,%3}, {%4,%5,%6,%7}, {%8,%9}, {%0,%1,%2,%3};"
        : "+r"(d[0]), "+r"(d[1]), "+r"(d[2]), "+r"(d[3])
        : "r"(a[0]), "r"(a[1]), "r"(a[2]), "r"(a[3]), "r"(b0), "r"(b1));
}

// ============================================================================
// Precompute kernels
// ============================================================================
__global__ void reset_max_kernel() { g_maxbits = 0u; }

__global__ void maxabs_kernel(const float* __restrict__ x, int count) {
    float m = 0.0f;
    for (int i = blockIdx.x * blockDim.x + threadIdx.x; i < count;
         i += gridDim.x * blockDim.x)
        m = fmaxf(m, fabsf(x[i]));
    #pragma unroll
    for (int o = 16; o; o >>= 1) m = fmaxf(m, __shfl_xor_sync(~0u, m, o));
    if ((threadIdx.x & 31) == 0) atomicMax(&g_maxbits, __float_as_uint(m));
}

__global__ void split_kernel(const float* __restrict__ src,
                             __nv_bfloat16* __restrict__ hi,
                             __nv_bfloat16* __restrict__ lo, long count)
{
    long i = (long)blockIdx.x * 1024 + threadIdx.x * 4;
    if (i + 3 >= count) {
        for (long k = i; k < count; k++) {
            float v = src[k];
            __nv_bfloat16 h = __float2bfloat16(v);
            hi[k] = h;
            lo[k] = __float2bfloat16(v - __bfloat162float(h));
        }
        return;
    }
    float4 v4 = *reinterpret_cast<const float4*>(src + i);
    float vs[4] = {v4.x, v4.y, v4.z, v4.w};
    __nv_bfloat16 h4[4], l4[4];
    #pragma unroll
    for (int j = 0; j < 4; j++) {
        h4[j] = __float2bfloat16(vs[j]);
        l4[j] = __float2bfloat16(vs[j] - __bfloat162float(h4[j]));
    }
    *reinterpret_cast<uint2*>(hi + i) = *reinterpret_cast<uint2*>(h4);
    *reinterpret_cast<uint2*>(lo + i) = *reinterpret_cast<uint2*>(l4);
}

__global__ void transpose_u_split_kernel(const float* __restrict__ u,
                                         __nv_bfloat16* __restrict__ hi,
                                         __nv_bfloat16* __restrict__ lo)
{
    __shared__ float t[32][33];
    int b0 = blockIdx.x * 32;
    int d0 = blockIdx.y * 32;
    int x = threadIdx.x, y = threadIdx.y;
    t[y][x] = u[(long)(b0 + y) * 64 + (d0 + x)];
    __syncthreads();
    float v = t[x][y];
    __nv_bfloat16 h = __float2bfloat16(v);
    hi[(long)(d0 + y) * 1024 + (b0 + x)] = h;
    lo[(long)(d0 + y) * 1024 + (b0 + x)] = __float2bfloat16(v - __bfloat162float(h));
}

// Sliding-window A, quantized to 2-digit int8: q = rint(x*S), q = 128*q1 + q0
__global__ void build_Aq_kernel(const float* __restrict__ xi,
                                signed char* __restrict__ Aq1,
                                signed char* __restrict__ Aq0)
{
    const int n = blockIdx.x;
    const float maxA = __uint_as_float(g_maxbits);
    const float S = 16256.0f / maxA;
    for (int kg = threadIdx.x; kg < 1040; kg += 256) {
        int k = kg * 4;
        char4 c1, c0;
        signed char* p1 = (signed char*)&c1;
        signed char* p0 = (signed char*)&c0;
        #pragma unroll
        for (int e = 0; e < 4; e++) {
            int kk = k + e;
            int m = kk / 65;
            int j = kk - m * 65;
            float v = xi[m * 4160 + n + j];
            int q = __float2int_rn(v * S);
            int q1 = (q + 64) >> 7;
            p1[e] = (signed char)q1;
            p0[e] = (signed char)(q - (q1 << 7));
        }
        *reinterpret_cast<char4*>(Aq1 + (long)n * 4160 + k) = c1;
        *reinterpret_cast<char4*>(Aq0 + (long)n * 4160 + k) = c0;
    }
}

// Transpose+quantize G: (4160 x 1024 bf16 hi/lo) -> Bq (1024 x 4160 int8 digits)
__global__ void quantB_kernel(const __nv_bfloat16* __restrict__ Bhi,
                              const __nv_bfloat16* __restrict__ Blo,
                              signed char* __restrict__ Bq1,
                              signed char* __restrict__ Bq0)
{
    __shared__ float t[32][33];
    int k0 = blockIdx.x * 32;
    int b0 = blockIdx.y * 32;
    int x = threadIdx.x, y = threadIdx.y;
    long gi = (long)(k0 + y) * 1024 + b0 + x;
    t[y][x] = __bfloat162float(Bhi[gi]) + __bfloat162float(Blo[gi]);
    __syncthreads();
    float v = t[x][y];  // = G[k0+x][b0+y]
    int q = __float2int_rn(v * 16256.0f);
    int q1 = (q + 64) >> 7;
    long go = (long)(b0 + y) * 4160 + k0 + x;
    Bq1[go] = (signed char)q1;
    Bq0[go] = (signed char)(q - (q1 << 7));
}

// ============================================================================
// MLP layer (round-5, measured best): bf16 split mma.sync, 3-stage ring
// ============================================================================
#define ASTRIDE 80
#define BSTRIDE 272
#define A_TILE  (128 * ASTRIDE)
#define B_TILE  (32 * BSTRIDE)
#define STAGE   (2 * A_TILE + 2 * B_TILE)
#define NSTAGES 3
#define MLP_SMEM_TOTAL (NSTAGES * STAGE)
#define OFF_AH  0
#define OFF_AL  A_TILE
#define OFF_BH  (2 * A_TILE)
#define OFF_BL  (2 * A_TILE + B_TILE)

__global__ __launch_bounds__(256, 2) void mlp_mma_kernel(
    const __nv_bfloat16* __restrict__ Whi, const __nv_bfloat16* __restrict__ Wlo,
    long wStride,
    const __nv_bfloat16* __restrict__ Xhi, const __nv_bfloat16* __restrict__ Xlo,
    long xStride,
    const float* __restrict__ bias_all, int biasStride,
    __nv_bfloat16* __restrict__ Yhi, __nv_bfloat16* __restrict__ Ylo,
    long yStride,
    int rows, int K)
{
    extern __shared__ char smem[];
    const uint32_t sb = smem_u32(smem);
    const int tid = threadIdx.x;
    const int lane = tid & 31;
    const int wid = tid >> 5;
    const int wm = wid & 3;
    const int wn = wid >> 2;
    const int m = blockIdx.z;
    const int row0 = blockIdx.y * 128;
    const int col0 = blockIdx.x * 128;

    const __nv_bfloat16* Ah = Whi + (long)m * wStride;
    const __nv_bfloat16* Al = Wlo + (long)m * wStride;
    const __nv_bfloat16* Bh = Xhi + (long)m * xStride;
    const __nv_bfloat16* Bl = Xlo + (long)m * xStride;
    const float* bias = bias_all + (long)m * biasStride;

    float acc[2][8][4];
    #pragma unroll
    for (int mi = 0; mi < 2; mi++)
        #pragma unroll
        for (int nj = 0; nj < 8; nj++)
            #pragma unroll
            for (int q = 0; q < 4; q++) acc[mi][nj][q] = 0.0f;

    const int quad = lane >> 3;
    const int r8 = lane & 7;
    const uint32_t aoff = (wm * 32 + (quad & 1) * 8 + r8) * ASTRIDE + (quad >> 1) * 16;
    const uint32_t boff = ((quad & 1) * 8 + r8) * BSTRIDE + (wn * 64 + (quad >> 1) * 8) * 2;

    const int nChunks = K >> 5;

    auto load = [&](int stageIdx, int k0) {
        uint32_t sbase = sb + (uint32_t)stageIdx * STAGE;
        #pragma unroll
        for (int i = 0; i < 2; i++) {
            int idx = tid + i * 256;
            int r = idx >> 2;
            int c = idx & 3;
            int gr = row0 + r;
            bool ok = gr < rows;
            long g = (long)(ok ? gr : 0) * K + k0 + c * 8;
            uint32_t d = r * ASTRIDE + c * 16;
            cp16z(sbase + OFF_AH + d, Ah + g, ok);
            cp16z(sbase + OFF_AL + d, Al + g, ok);
        }
        #pragma unroll
        for (int i = 0; i < 2; i++) {
            int idx = tid + i * 256;
            int r = idx >> 4;
            int c = idx & 15;
            long g = (long)(k0 + r) * 1024 + col0 + c * 8;
            uint32_t d = r * BSTRIDE + c * 16;
            cp16(sbase + OFF_BH + d, Bh + g);
            cp16(sbase + OFF_BL + d, Bl + g);
        }
    };

    load(0, 0);
    CP_COMMIT();
    if (nChunks > 1) load(1, 32);
    CP_COMMIT();

    int curStage = 0, nxtStage = 2;
    for (int t = 0; t < nChunks; t++) {
        CP_WAIT(1);
        __syncthreads();
        if (t + 2 < nChunks) load(nxtStage, (t + 2) * 32);
        CP_COMMIT();

        const uint32_t cur = sb + (uint32_t)curStage * STAGE;
        curStage = (curStage == NSTAGES - 1) ? 0 : curStage + 1;
        nxtStage = (nxtStage == NSTAGES - 1) ? 0 : nxtStage + 1;

        #pragma unroll
        for (int ks = 0; ks < 2; ks++) {
            uint32_t ah[2][4], al[2][4];
            ldsm_x4(ah[0], cur + OFF_AH + aoff + ks * 32);
            ldsm_x4(ah[1], cur + OFF_AH + aoff + 16 * ASTRIDE + ks * 32);
            ldsm_x4(al[0], cur + OFF_AL + aoff + ks * 32);
            ldsm_x4(al[1], cur + OFF_AL + aoff + 16 * ASTRIDE + ks * 32);

            #pragma unroll
            for (int g = 0; g < 4; g++) {
                uint32_t rh[4], rl[4];
                ldsm_x4t(rh, cur + OFF_BH + boff + g * 32 + ks * 16 * BSTRIDE);
                ldsm_x4t(rl, cur + OFF_BL + boff + g * 32 + ks * 16 * BSTRIDE);
                mma_bf16(acc[0][2 * g],     ah[0], &rh[0]);
                mma_bf16(acc[0][2 * g + 1], ah[0], &rh[2]);
                mma_bf16(acc[1][2 * g],     ah[1], &rh[0]);
                mma_bf16(acc[1][2 * g + 1], ah[1], &rh[2]);
                mma_bf16(acc[0][2 * g],     ah[0], &rl[0]);
                mma_bf16(acc[0][2 * g + 1], ah[0], &rl[2]);
                mma_bf16(acc[1][2 * g],     ah[1], &rl[0]);
                mma_bf16(acc[1][2 * g + 1], ah[1], &rl[2]);
                mma_bf16(acc[0][2 * g],     al[0], &rh[0]);
                mma_bf16(acc[0][2 * g + 1], al[0], &rh[2]);
                mma_bf16(acc[1][2 * g],     al[1], &rh[0]);
                mma_bf16(acc[1][2 * g + 1], al[1], &rh[2]);
            }
        }
        __syncthreads();
    }

    const int grp = lane >> 2;
    const int qid = lane & 3;
    __nv_bfloat16* yh = Yhi + (long)m * yStride;
    __nv_bfloat16* yl = Ylo + (long)m * yStride;
    #pragma unroll
    for (int mi = 0; mi < 2; mi++) {
        int rbase = row0 + wm * 32 + mi * 16;
        #pragma unroll
        for (int half = 0; half < 2; half++) {
            int gr = rbase + grp + half * 8;
            if (gr >= rows) continue;
            float bv = bias[gr];
            #pragma unroll
            for (int nj = 0; nj < 8; nj++) {
                int cn = col0 + wn * 64 + nj * 8 + qid * 2;
                float y0 = sigmoidf_fast(acc[mi][nj][2 * half + 0] + bv);
                float y1 = sigmoidf_fast(acc[mi][nj][2 * half + 1] + bv);
                __nv_bfloat16 h0 = __float2bfloat16(y0);
                __nv_bfloat16 h1 = __float2bfloat16(y1);
                __nv_bfloat16 l0 = __float2bfloat16(y0 - __bfloat162float(h0));
                __nv_bfloat16 l1 = __float2bfloat16(y1 - __bfloat162float(h1));
                __nv_bfloat162 hp; hp.x = h0; hp.y = h1;
                __nv_bfloat162 lp; lp.x = l0; lp.y = l1;
                *reinterpret_cast<__nv_bfloat162*>(yh + (long)gr * 1024 + cn) = hp;
                *reinterpret_cast<__nv_bfloat162*>(yl + (long)gr * 1024 + cn) = lp;
            }
        }
    }
}

// ============================================================================
// Output GEMM, int8 IMMA:
//   out(4096x1024) = A(4096x4160) @ B(4160x1024)
//   A digits row-major (n x k); B digits stored transposed (b x k) so plain
//   ldmatrix feeds the .row.col B fragments. 3 IMMAs per k32 (drop a0*b0).
//   CTA 128x128, 512 threads (16 warps, m32 x n32 each), 3-stage ring.
// ============================================================================
#define QSTRIDE 48
#define QS_A1 0
#define QS_A0 (128 * QSTRIDE)
#define QS_B1 (2 * 128 * QSTRIDE)
#define QS_B0 (3 * 128 * QSTRIDE)
#define QSTAGE (4 * 128 * QSTRIDE)      // 24576
#define QNST 3
#define OUT_SMEM_TOTAL (QNST * QSTAGE)  // 73728

__global__ __launch_bounds__(512) void out_imma_kernel(
    const signed char* __restrict__ Aq1, const signed char* __restrict__ Aq0,
    const signed char* __restrict__ Bq1, const signed char* __restrict__ Bq0,
    float* __restrict__ out)
{
    extern __shared__ char smem[];
    const uint32_t sb = smem_u32(smem);
    const int tid = threadIdx.x;
    const int lane = tid & 31;
    const int wid = tid >> 5;
    const int wm = wid & 3;      // 4 m-warps, 32 rows each
    const int wn = wid >> 2;     // 4 n-warps, 32 cols each
    const int n0 = blockIdx.y * 128;
    const int col0 = blockIdx.x * 128;

    int hi[2][4][4], mid[2][4][4];
    #pragma unroll
    for (int mi = 0; mi < 2; mi++)
        #pragma unroll
        for (int nj = 0; nj < 4; nj++)
            #pragma unroll
            for (int q = 0; q < 4; q++) { hi[mi][nj][q] = 0; mid[mi][nj][q] = 0; }

    // ldmatrix lane addressing:
    // A (m16 x k32 tile): row = lane&15, byteCol = (lane>>4)*16
    const uint32_t aoff = (uint32_t)(lane & 15) * QSTRIDE + (uint32_t)(lane >> 4) * 16;
    // B^T (n16 x k32 tile): row = (lane&7) + ((lane>>4)<<3), byteCol = ((lane>>3)&1)*16
    const uint32_t boff =
        (uint32_t)((lane & 7) + ((lane >> 4) << 3)) * QSTRIDE +
        (uint32_t)((lane >> 3) & 1) * 16;

    auto load = [&](int stageIdx, int k0) {
        uint32_t sbase = sb + (uint32_t)stageIdx * QSTAGE;
        int r = (tid & 255) >> 1;
        int c = tid & 1;
        uint32_t d = (uint32_t)r * QSTRIDE + (uint32_t)c * 16;
        if (tid < 256) {
            long g = (long)(n0 + r) * 4160 + k0 + c * 16;
            cp16(sbase + QS_A1 + d, Aq1 + g);
            cp16(sbase + QS_A0 + d, Aq0 + g);
        } else {
            long g = (long)(col0 + r) * 4160 + k0 + c * 16;
            cp16(sbase + QS_B1 + d, Bq1 + g);
            cp16(sbase + QS_B0 + d, Bq0 + g);
        }
    };

    load(0, 0);
    CP_COMMIT();
    load(1, 32);
    CP_COMMIT();

    int curStage = 0, nxtStage = 2;
    for (int t = 0; t < 130; t++) {
        CP_WAIT(1);
        __syncthreads();
        if (t + 2 < 130) load(nxtStage, (t + 2) * 32);
        CP_COMMIT();

        const uint32_t cur = sb + (uint32_t)curStage * QSTAGE;
        curStage = (curStage == QNST - 1) ? 0 : curStage + 1;
        nxtStage = (nxtStage == QNST - 1) ? 0 : nxtStage + 1;

        uint32_t a1f[2][4], a0f[2][4];
        ldsm_x4(a1f[0], cur + QS_A1 + (uint32_t)(wm * 32) * QSTRIDE + aoff);
        ldsm_x4(a1f[1], cur + QS_A1 + (uint32_t)(wm * 32 + 16) * QSTRIDE + aoff);
        ldsm_x4(a0f[0], cur + QS_A0 + (uint32_t)(wm * 32) * QSTRIDE + aoff);
        ldsm_x4(a0f[1], cur + QS_A0 + (uint32_t)(wm * 32 + 16) * QSTRIDE + aoff);

        uint32_t b1f[2][4], b0f[2][4];
        ldsm_x4(b1f[0], cur + QS_B1 + (uint32_t)(wn * 32) * QSTRIDE + boff);
        ldsm_x4(b1f[1], cur + QS_B1 + (uint32_t)(wn * 32 + 16) * QSTRIDE + boff);
        ldsm_x4(b0f[0], cur + QS_B0 + (uint32_t)(wn * 32) * QSTRIDE + boff);
        ldsm_x4(b0f[1], cur + QS_B0 + (uint32_t)(wn * 32 + 16) * QSTRIDE + boff);

        #pragma unroll
        for (int mi = 0; mi < 2; mi++)
            #pragma unroll
            for (int nj = 0; nj < 4; nj++) {
                int h = nj >> 1, p = (nj & 1) * 2;
                mma_s8(hi[mi][nj],  a1f[mi], b1f[h][p], b1f[h][p + 1]);
                mma_s8(mid[mi][nj], a1f[mi], b0f[h][p], b0f[h][p + 1]);
                mma_s8(mid[mi][nj], a0f[mi], b1f[h][p], b1f[h][p + 1]);
            }
        __syncthreads();
    }

    // dequant epilogue: out = (16384*hi + 128*mid) / (S_A * S_B)
    const float maxA = __uint_as_float(g_maxbits);
    const float inv = maxA / (16256.0f * 16256.0f);
    const int grp = lane >> 2;
    const int qid = lane & 3;
    #pragma unroll
    for (int mi = 0; mi < 2; mi++) {
        int rbase = n0 + wm * 32 + mi * 16;
        #pragma unroll
        for (int nj = 0; nj < 4; nj++) {
            int cn = col0 + wn * 32 + nj * 8 + qid * 2;
            float v0 = fmaf(16384.0f, (float)hi[mi][nj][0],
                            128.0f * (float)mid[mi][nj][0]) * inv;
            float v1 = fmaf(16384.0f, (float)hi[mi][nj][1],
                            128.0f * (float)mid[mi][nj][1]) * inv;
            float v2 = fmaf(16384.0f, (float)hi[mi][nj][2],
                            128.0f * (float)mid[mi][nj][2]) * inv;
            float v3 = fmaf(16384.0f, (float)hi[mi][nj][3],
                            128.0f * (float)mid[mi][nj][3]) * inv;
            *reinterpret_cast<float2*>(&out[(long)(rbase + grp) * 1024 + cn]) =
                make_float2(v0, v1);
            *reinterpret_cast<float2*>(&out[(long)(rbase + grp + 8) * 1024 + cn]) =
                make_float2(v2, v3);
        }
    }
}

// ============================================================================
// Launch
// ============================================================================
extern "C" void kernel_launch(void* const* d_in, const int* in_sizes, int n_in,
                              void* d_out, int out_size) {
    const float* u  = (const float*)d_in[0];
    const float* w0 = (const float*)d_in[1];
    const float* b0 = (const float*)d_in[2];
    const float* w  = (const float*)d_in[3];
    const float* b  = (const float*)d_in[4];
    const float* wf = (const float*)d_in[5];
    const float* bf = (const float*)d_in[6];
    const float* xi = (const float*)d_in[7];
    float* out = (float*)d_out;

    void* p;
    cudaGetSymbolAddress(&p, g_uThi);  __nv_bfloat16* uThi = (__nv_bfloat16*)p;
    cudaGetSymbolAddress(&p, g_uTlo);  __nv_bfloat16* uTlo = (__nv_bfloat16*)p;
    cudaGetSymbolAddress(&p, g_W0hi);  __nv_bfloat16* W0hi = (__nv_bfloat16*)p;
    cudaGetSymbolAddress(&p, g_W0lo);  __nv_bfloat16* W0lo = (__nv_bfloat16*)p;
    cudaGetSymbolAddress(&p, g_Whi);   __nv_bfloat16* Whi  = (__nv_bfloat16*)p;
    cudaGetSymbolAddress(&p, g_Wlo);   __nv_bfloat16* Wlo  = (__nv_bfloat16*)p;
    cudaGetSymbolAddress(&p, g_Wfhi);  __nv_bfloat16* Wfhi = (__nv_bfloat16*)p;
    cudaGetSymbolAddress(&p, g_Wflo);  __nv_bfloat16* Wflo = (__nv_bfloat16*)p;
    cudaGetSymbolAddress(&p, g_actAhi); __nv_bfloat16* aAhi = (__nv_bfloat16*)p;
    cudaGetSymbolAddress(&p, g_actAlo); __nv_bfloat16* aAlo = (__nv_bfloat16*)p;
    cudaGetSymbolAddress(&p, g_actBhi); __nv_bfloat16* aBhi = (__nv_bfloat16*)p;
    cudaGetSymbolAddress(&p, g_actBlo); __nv_bfloat16* aBlo = (__nv_bfloat16*)p;
    cudaGetSymbolAddress(&p, g_Bhi);   __nv_bfloat16* Bhi = (__nv_bfloat16*)p;
    cudaGetSymbolAddress(&p, g_Blo);   __nv_bfloat16* Blo = (__nv_bfloat16*)p;
    cudaGetSymbolAddress(&p, g_Aq1);   signed char* Aq1 = (signed char*)p;
    cudaGetSymbolAddress(&p, g_Aq0);   signed char* Aq0 = (signed char*)p;
    cudaGetSymbolAddress(&p, g_Bq1);   signed char* Bq1 = (signed char*)p;
    cudaGetSymbolAddress(&p, g_Bq0);   signed char* Bq0 = (signed char*)p;

    cudaFuncSetAttribute(mlp_mma_kernel,
                         cudaFuncAttributeMaxDynamicSharedMemorySize, MLP_SMEM_TOTAL);
    cudaFuncSetAttribute(out_imma_kernel,
                         cudaFuncAttributeMaxDynamicSharedMemorySize, OUT_SMEM_TOTAL);

    // ---- scale + quantized A build ----
    reset_max_kernel<<<1, 1>>>();
    maxabs_kernel<<<256, 256>>>(xi, 64 * 4160);
    build_Aq_kernel<<<4096, 256>>>(xi, Aq1, Aq0);

    // ---- weight splits + uT ----
    {
        long c0 = 64L * 256 * 64;
        split_kernel<<<(unsigned)((c0 + 1023) / 1024), 256>>>(w0, W0hi, W0lo, c0);
        long c1 = 3L * 64 * 256 * 256;
        split_kernel<<<(unsigned)((c1 + 1023) / 1024), 256>>>(w, Whi, Wlo, c1);
        long c2 = 64L * 65 * 256;
        split_kernel<<<(unsigned)((c2 + 1023) / 1024), 256>>>(wf, Wfhi, Wflo, c2);
    }
    transpose_u_split_kernel<<<dim3(32, 2), dim3(32, 32)>>>(u, uThi, uTlo);

    // ---- MLP chain (round-5 structure) ----
    mlp_mma_kernel<<<dim3(8, 2, 64), 256, MLP_SMEM_TOTAL>>>(
        W0hi, W0lo, 256L * 64, uThi, uTlo, 0L, b0, 256,
        aAhi, aAlo, 256L * 1024, 256, 64);

    const __nv_bfloat16* sh = aAhi; const __nv_bfloat16* sl = aAlo;
    __nv_bfloat16* dh = aBhi; __nv_bfloat16* dl = aBlo;
    for (int i = 0; i < 3; i++) {
        mlp_mma_kernel<<<dim3(8, 2, 64), 256, MLP_SMEM_TOTAL>>>(
            Whi + (long)i * 64 * 256 * 256, Wlo + (long)i * 64 * 256 * 256,
            256L * 256, sh, sl, 256L * 1024,
            b + (long)i * 64 * 256, 256,
            dh, dl, 256L * 1024, 256, 256);
        const __nv_bfloat16* th = sh; const __nv_bfloat16* tl = sl;
        sh = dh; sl = dl;
        dh = (__nv_bfloat16*)th; dl = (__nv_bfloat16*)tl;
    }

    // final layer: rows=65 -> G as bf16 hi/lo (4160 x 1024)
    mlp_mma_kernel<<<dim3(8, 1, 64), 256, MLP_SMEM_TOTAL>>>(
        Wfhi, Wflo, 65L * 256, sh, sl, 256L * 1024, bf, 65,
        Bhi, Blo, 65L * 1024, 65, 256);

    // quantize + transpose G -> B^T int8 digits
    quantB_kernel<<<dim3(130, 32), dim3(32, 32)>>>(Bhi, Blo, Bq1, Bq0);

    // ---- int8 output GEMM ----
    out_imma_kernel<<<dim3(8, 32), 512, OUT_SMEM_TOTAL>>>(Aq1, Aq0, Bq1, Bq0, out);
}

// round 11
// speedup vs baseline: 2.1715x; 2.1715x over previous
#include <cuda_runtime.h>
#include <cuda_bf16.h>
#include <cuda_fp16.h>
#include <cstdint>

// ============================================================================
// spectralNNDeepshared2 — Round 8:
//   MLP chain: round-5 bf16 3-term split mma.sync (measured best, unchanged)
//   Output contraction: fp16 2-term (A = exact fp16 hi/lo digits, B = single
//   fp16) -> 2/3 the HMMA instructions and half the B smem traffic.
//   Final MLP layer writes G directly as fp16 (mode flag).
// ============================================================================

// ---------------- scratch ----------------
__device__ __nv_bfloat16 g_uThi[64 * 1024];
__device__ __nv_bfloat16 g_uTlo[64 * 1024];
__device__ __nv_bfloat16 g_W0hi[64 * 256 * 64];
__device__ __nv_bfloat16 g_W0lo[64 * 256 * 64];
__device__ __nv_bfloat16 g_Whi[3L * 64 * 256 * 256];
__device__ __nv_bfloat16 g_Wlo[3L * 64 * 256 * 256];
__device__ __nv_bfloat16 g_Wfhi[64 * 65 * 256];
__device__ __nv_bfloat16 g_Wflo[64 * 65 * 256];
__device__ __nv_bfloat16 g_actAhi[64L * 256 * 1024];
__device__ __nv_bfloat16 g_actAlo[64L * 256 * 1024];
__device__ __nv_bfloat16 g_actBhi[64L * 256 * 1024];
__device__ __nv_bfloat16 g_actBlo[64L * 256 * 1024];
__device__ __half g_Ah16[4096L * 4160];
__device__ __half g_Al16[4096L * 4160];
__device__ __half g_G16[4160L * 1024];

__device__ __forceinline__ float sigmoidf_fast(float x) {
    return 1.0f / (1.0f + __expf(-x));
}
__device__ __forceinline__ uint32_t smem_u32(const void* p) {
    uint32_t a;
    asm("{ .reg .u64 t; cvta.to.shared.u64 t, %1; cvt.u32.u64 %0, t; }"
        : "=r"(a) : "l"(p));
    return a;
}

// ---------------- cp.async / ldmatrix / mma helpers ----------------
__device__ __forceinline__ void cp16(uint32_t dst, const void* src) {
    asm volatile("cp.async.cg.shared.global [%0], [%1], 16;\n"
                 :: "r"(dst), "l"(src));
}
__device__ __forceinline__ void cp16z(uint32_t dst, const void* src, bool valid) {
    int sz = valid ? 16 : 0;
    asm volatile("cp.async.cg.shared.global [%0], [%1], 16, %2;\n"
                 :: "r"(dst), "l"(src), "r"(sz));
}
#define CP_COMMIT() asm volatile("cp.async.commit_group;\n" ::: "memory")
#define CP_WAIT(n)  asm volatile("cp.async.wait_group %0;\n" :: "n"(n) : "memory")

__device__ __forceinline__ void ldsm_x4(uint32_t* r, uint32_t addr) {
    asm volatile("ldmatrix.sync.aligned.m8n8.x4.shared.b16 {%0,%1,%2,%3}, [%4];"
        : "=r"(r[0]), "=r"(r[1]), "=r"(r[2]), "=r"(r[3]) : "r"(addr));
}
__device__ __forceinline__ void ldsm_x4t(uint32_t* r, uint32_t addr) {
    asm volatile("ldmatrix.sync.aligned.m8n8.x4.trans.shared.b16 {%0,%1,%2,%3}, [%4];"
        : "=r"(r[0]), "=r"(r[1]), "=r"(r[2]), "=r"(r[3]) : "r"(addr));
}
__device__ __forceinline__ void mma_bf16(float* d, const uint32_t* a, const uint32_t* b) {
    asm volatile(
        "mma.sync.aligned.m16n8k16.row.col.f32.bf16.bf16.f32 "
        "{%0,%1,%2,%3}, {%4,%5,%6,%7}, {%8,%9}, {%0,%1,%2,%3};"
        : "+f"(d[0]), "+f"(d[1]), "+f"(d[2]), "+f"(d[3])
        : "r"(a[0]), "r"(a[1]), "r"(a[2]), "r"(a[3]), "r"(b[0]), "r"(b[1]));
}
__device__ __forceinline__ void mma_f16(float* d, const uint32_t* a, const uint32_t* b) {
    asm volatile(
        "mma.sync.aligned.m16n8k16.row.col.f32.f16.f16.f32 "
        "{%0,%1,%2,%3}, {%4,%5,%6,%7}, {%8,%9}, {%0,%1,%2,%3};"
        : "+f"(d[0]), "+f"(d[1]), "+f"(d[2]), "+f"(d[3])
        : "r"(a[0]), "r"(a[1]), "r"(a[2]), "r"(a[3]), "r"(b[0]), "r"(b[1]));
}

// ============================================================================
// Precompute kernels
// ============================================================================
__global__ void split_kernel(const float* __restrict__ src,
                             __nv_bfloat16* __restrict__ hi,
                             __nv_bfloat16* __restrict__ lo, long count)
{
    long i = (long)blockIdx.x * 1024 + threadIdx.x * 4;
    if (i + 3 >= count) {
        for (long k = i; k < count; k++) {
            float v = src[k];
            __nv_bfloat16 h = __float2bfloat16(v);
            hi[k] = h;
            lo[k] = __float2bfloat16(v - __bfloat162float(h));
        }
        return;
    }
    float4 v4 = *reinterpret_cast<const float4*>(src + i);
    float vs[4] = {v4.x, v4.y, v4.z, v4.w};
    __nv_bfloat16 h4[4], l4[4];
    #pragma unroll
    for (int j = 0; j < 4; j++) {
        h4[j] = __float2bfloat16(vs[j]);
        l4[j] = __float2bfloat16(vs[j] - __bfloat162float(h4[j]));
    }
    *reinterpret_cast<uint2*>(hi + i) = *reinterpret_cast<uint2*>(h4);
    *reinterpret_cast<uint2*>(lo + i) = *reinterpret_cast<uint2*>(l4);
}

__global__ void transpose_u_split_kernel(const float* __restrict__ u,
                                         __nv_bfloat16* __restrict__ hi,
                                         __nv_bfloat16* __restrict__ lo)
{
    __shared__ float t[32][33];
    int b0 = blockIdx.x * 32;
    int d0 = blockIdx.y * 32;
    int x = threadIdx.x, y = threadIdx.y;
    t[y][x] = u[(long)(b0 + y) * 64 + (d0 + x)];
    __syncthreads();
    float v = t[x][y];
    __nv_bfloat16 h = __float2bfloat16(v);
    hi[(long)(d0 + y) * 1024 + (b0 + x)] = h;
    lo[(long)(d0 + y) * 1024 + (b0 + x)] = __float2bfloat16(v - __bfloat162float(h));
}

// Sliding-window A (4096 x 4160) as exact fp16 hi/lo digits
__global__ void build_A16_kernel(const float* __restrict__ xi,
                                 __half* __restrict__ Ah,
                                 __half* __restrict__ Al)
{
    int n = blockIdx.x;
    for (int k = threadIdx.x; k < 4160; k += 256) {
        int m = k / 65;
        int j = k - m * 65;
        float v = xi[m * 4160 + n + j];
        __half h = __float2half_rn(v);
        Ah[(long)n * 4160 + k] = h;
        Al[(long)n * 4160 + k] = __float2half_rn(v - __half2float(h));
    }
}

// ============================================================================
// MLP layer (round-5 structure): bf16 3-term split mma.sync, 3-stage ring.
// mode 0: write bf16 hi/lo activation pair. mode 1: write single fp16 (G).
// ============================================================================
#define ASTRIDE 80
#define BSTRIDE 272
#define A_TILE  (128 * ASTRIDE)
#define B_TILE  (32 * BSTRIDE)
#define STAGE   (2 * A_TILE + 2 * B_TILE)
#define NSTAGES 3
#define MLP_SMEM_TOTAL (NSTAGES * STAGE)
#define OFF_AH  0
#define OFF_AL  A_TILE
#define OFF_BH  (2 * A_TILE)
#define OFF_BL  (2 * A_TILE + B_TILE)

__global__ __launch_bounds__(256, 2) void mlp_mma_kernel(
    const __nv_bfloat16* __restrict__ Whi, const __nv_bfloat16* __restrict__ Wlo,
    long wStride,
    const __nv_bfloat16* __restrict__ Xhi, const __nv_bfloat16* __restrict__ Xlo,
    long xStride,
    const float* __restrict__ bias_all, int biasStride,
    __nv_bfloat16* __restrict__ Yhi, __nv_bfloat16* __restrict__ Ylo,
    long yStride,
    int rows, int K, int mode)
{
    extern __shared__ char smem[];
    const uint32_t sb = smem_u32(smem);
    const int tid = threadIdx.x;
    const int lane = tid & 31;
    const int wid = tid >> 5;
    const int wm = wid & 3;
    const int wn = wid >> 2;
    const int m = blockIdx.z;
    const int row0 = blockIdx.y * 128;
    const int col0 = blockIdx.x * 128;

    const __nv_bfloat16* Ah = Whi + (long)m * wStride;
    const __nv_bfloat16* Al = Wlo + (long)m * wStride;
    const __nv_bfloat16* Bh = Xhi + (long)m * xStride;
    const __nv_bfloat16* Bl = Xlo + (long)m * xStride;
    const float* bias = bias_all + (long)m * biasStride;

    float acc[2][8][4];
    #pragma unroll
    for (int mi = 0; mi < 2; mi++)
        #pragma unroll
        for (int nj = 0; nj < 8; nj++)
            #pragma unroll
            for (int q = 0; q < 4; q++) acc[mi][nj][q] = 0.0f;

    const int quad = lane >> 3;
    const int r8 = lane & 7;
    const uint32_t aoff = (wm * 32 + (quad & 1) * 8 + r8) * ASTRIDE + (quad >> 1) * 16;
    const uint32_t boff = ((quad & 1) * 8 + r8) * BSTRIDE + (wn * 64 + (quad >> 1) * 8) * 2;

    const int nChunks = K >> 5;

    auto load = [&](int stageIdx, int k0) {
        uint32_t sbase = sb + (uint32_t)stageIdx * STAGE;
        #pragma unroll
        for (int i = 0; i < 2; i++) {
            int idx = tid + i * 256;
            int r = idx >> 2;
            int c = idx & 3;
            int gr = row0 + r;
            bool ok = gr < rows;
            long g = (long)(ok ? gr : 0) * K + k0 + c * 8;
            uint32_t d = r * ASTRIDE + c * 16;
            cp16z(sbase + OFF_AH + d, Ah + g, ok);
            cp16z(sbase + OFF_AL + d, Al + g, ok);
        }
        #pragma unroll
        for (int i = 0; i < 2; i++) {
            int idx = tid + i * 256;
            int r = idx >> 4;
            int c = idx & 15;
            long g = (long)(k0 + r) * 1024 + col0 + c * 8;
            uint32_t d = r * BSTRIDE + c * 16;
            cp16(sbase + OFF_BH + d, Bh + g);
            cp16(sbase + OFF_BL + d, Bl + g);
        }
    };

    load(0, 0);
    CP_COMMIT();
    if (nChunks > 1) load(1, 32);
    CP_COMMIT();

    int curStage = 0, nxtStage = 2;
    for (int t = 0; t < nChunks; t++) {
        CP_WAIT(1);
        __syncthreads();
        if (t + 2 < nChunks) load(nxtStage, (t + 2) * 32);
        CP_COMMIT();

        const uint32_t cur = sb + (uint32_t)curStage * STAGE;
        curStage = (curStage == NSTAGES - 1) ? 0 : curStage + 1;
        nxtStage = (nxtStage == NSTAGES - 1) ? 0 : nxtStage + 1;

        #pragma unroll
        for (int ks = 0; ks < 2; ks++) {
            uint32_t ah[2][4], al[2][4];
            ldsm_x4(ah[0], cur + OFF_AH + aoff + ks * 32);
            ldsm_x4(ah[1], cur + OFF_AH + aoff + 16 * ASTRIDE + ks * 32);
            ldsm_x4(al[0], cur + OFF_AL + aoff + ks * 32);
            ldsm_x4(al[1], cur + OFF_AL + aoff + 16 * ASTRIDE + ks * 32);

            #pragma unroll
            for (int g = 0; g < 4; g++) {
                uint32_t rh[4], rl[4];
                ldsm_x4t(rh, cur + OFF_BH + boff + g * 32 + ks * 16 * BSTRIDE);
                ldsm_x4t(rl, cur + OFF_BL + boff + g * 32 + ks * 16 * BSTRIDE);
                mma_bf16(acc[0][2 * g],     ah[0], &rh[0]);
                mma_bf16(acc[0][2 * g + 1], ah[0], &rh[2]);
                mma_bf16(acc[1][2 * g],     ah[1], &rh[0]);
                mma_bf16(acc[1][2 * g + 1], ah[1], &rh[2]);
                mma_bf16(acc[0][2 * g],     ah[0], &rl[0]);
                mma_bf16(acc[0][2 * g + 1], ah[0], &rl[2]);
                mma_bf16(acc[1][2 * g],     ah[1], &rl[0]);
                mma_bf16(acc[1][2 * g + 1], ah[1], &rl[2]);
                mma_bf16(acc[0][2 * g],     al[0], &rh[0]);
                mma_bf16(acc[0][2 * g + 1], al[0], &rh[2]);
                mma_bf16(acc[1][2 * g],     al[1], &rh[0]);
                mma_bf16(acc[1][2 * g + 1], al[1], &rh[2]);
            }
        }
        __syncthreads();
    }

    const int grp = lane >> 2;
    const int qid = lane & 3;
    __nv_bfloat16* yh = Yhi + (long)m * yStride;
    __nv_bfloat16* yl = Ylo + (long)m * yStride;
    #pragma unroll
    for (int mi = 0; mi < 2; mi++) {
        int rbase = row0 + wm * 32 + mi * 16;
        #pragma unroll
        for (int half = 0; half < 2; half++) {
            int gr = rbase + grp + half * 8;
            if (gr >= rows) continue;
            float bv = bias[gr];
            #pragma unroll
            for (int nj = 0; nj < 8; nj++) {
                int cn = col0 + wn * 64 + nj * 8 + qid * 2;
                float y0 = sigmoidf_fast(acc[mi][nj][2 * half + 0] + bv);
                float y1 = sigmoidf_fast(acc[mi][nj][2 * half + 1] + bv);
                if (mode == 0) {
                    __nv_bfloat16 h0 = __float2bfloat16(y0);
                    __nv_bfloat16 h1 = __float2bfloat16(y1);
                    __nv_bfloat16 l0 = __float2bfloat16(y0 - __bfloat162float(h0));
                    __nv_bfloat16 l1 = __float2bfloat16(y1 - __bfloat162float(h1));
                    __nv_bfloat162 hp; hp.x = h0; hp.y = h1;
                    __nv_bfloat162 lp; lp.x = l0; lp.y = l1;
                    *reinterpret_cast<__nv_bfloat162*>(yh + (long)gr * 1024 + cn) = hp;
                    *reinterpret_cast<__nv_bfloat162*>(yl + (long)gr * 1024 + cn) = lp;
                } else {
                    __half2 hp;
                    hp.x = __float2half_rn(y0);
                    hp.y = __float2half_rn(y1);
                    *reinterpret_cast<__half2*>(
                        reinterpret_cast<__half*>(yh) + (long)gr * 1024 + cn) = hp;
                }
            }
        }
    }
}

// ============================================================================
// Output GEMM, fp16 2-term:
//   out(4096x1024) = A(4096x4160) @ G(4160x1024)
//   A = exact fp16 digit pair (hi+lo), B = single fp16. 64 MMAs per k32 chunk.
// ============================================================================
#define OSTAGE (2 * A_TILE + B_TILE)        // 29184
#define OUT_SMEM_TOTAL (NSTAGES * OSTAGE)   // 87552
#define O_AH 0
#define O_AL A_TILE
#define O_B  (2 * A_TILE)

__global__ __launch_bounds__(256, 2) void out_mma_kernel(
    const __half* __restrict__ Ahi, const __half* __restrict__ Alo,
    const __half* __restrict__ Bg,
    float* __restrict__ out)
{
    extern __shared__ char smem[];
    const uint32_t sb = smem_u32(smem);
    const int tid = threadIdx.x;
    const int lane = tid & 31;
    const int wid = tid >> 5;
    const int wm = wid & 3;
    const int wn = wid >> 2;
    const int n0 = blockIdx.y * 128;
    const int col0 = blockIdx.x * 128;

    float acc[2][8][4];
    #pragma unroll
    for (int mi = 0; mi < 2; mi++)
        #pragma unroll
        for (int nj = 0; nj < 8; nj++)
            #pragma unroll
            for (int q = 0; q < 4; q++) acc[mi][nj][q] = 0.0f;

    const int quad = lane >> 3;
    const int r8 = lane & 7;
    const uint32_t aoff = (wm * 32 + (quad & 1) * 8 + r8) * ASTRIDE + (quad >> 1) * 16;
    const uint32_t boff = ((quad & 1) * 8 + r8) * BSTRIDE + (wn * 64 + (quad >> 1) * 8) * 2;

    auto load = [&](int stageIdx, int k0) {
        uint32_t sbase = sb + (uint32_t)stageIdx * OSTAGE;
        #pragma unroll
        for (int i = 0; i < 2; i++) {
            int idx = tid + i * 256;
            int r = idx >> 2;
            int c = idx & 3;
            long g = (long)(n0 + r) * 4160 + k0 + c * 8;
            uint32_t d = r * ASTRIDE + c * 16;
            cp16(sbase + O_AH + d, Ahi + g);
            cp16(sbase + O_AL + d, Alo + g);
        }
        #pragma unroll
        for (int i = 0; i < 2; i++) {
            int idx = tid + i * 256;
            int r = idx >> 4;
            int c = idx & 15;
            long g = (long)(k0 + r) * 1024 + col0 + c * 8;
            uint32_t d = r * BSTRIDE + c * 16;
            cp16(sbase + O_B + d, Bg + g);
        }
    };

    load(0, 0);
    CP_COMMIT();
    load(1, 32);
    CP_COMMIT();

    int curStage = 0, nxtStage = 2;
    for (int t = 0; t < 130; t++) {
        CP_WAIT(1);
        __syncthreads();
        if (t + 2 < 130) load(nxtStage, (t + 2) * 32);
        CP_COMMIT();

        const uint32_t cur = sb + (uint32_t)curStage * OSTAGE;
        curStage = (curStage == NSTAGES - 1) ? 0 : curStage + 1;
        nxtStage = (nxtStage == NSTAGES - 1) ? 0 : nxtStage + 1;

        #pragma unroll
        for (int ks = 0; ks < 2; ks++) {
            uint32_t ah[2][4], al[2][4];
            ldsm_x4(ah[0], cur + O_AH + aoff + ks * 32);
            ldsm_x4(ah[1], cur + O_AH + aoff + 16 * ASTRIDE + ks * 32);
            ldsm_x4(al[0], cur + O_AL + aoff + ks * 32);
            ldsm_x4(al[1], cur + O_AL + aoff + 16 * ASTRIDE + ks * 32);

            #pragma unroll
            for (int g = 0; g < 4; g++) {
                uint32_t rh[4];
                ldsm_x4t(rh, cur + O_B + boff + g * 32 + ks * 16 * BSTRIDE);
                mma_f16(acc[0][2 * g],     ah[0], &rh[0]);
                mma_f16(acc[0][2 * g + 1], ah[0], &rh[2]);
                mma_f16(acc[1][2 * g],     ah[1], &rh[0]);
                mma_f16(acc[1][2 * g + 1], ah[1], &rh[2]);
                mma_f16(acc[0][2 * g],     al[0], &rh[0]);
                mma_f16(acc[0][2 * g + 1], al[0], &rh[2]);
                mma_f16(acc[1][2 * g],     al[1], &rh[0]);
                mma_f16(acc[1][2 * g + 1], al[1], &rh[2]);
            }
        }
        __syncthreads();
    }

    const int grp = lane >> 2;
    const int qid = lane & 3;
    #pragma unroll
    for (int mi = 0; mi < 2; mi++) {
        int rbase = n0 + wm * 32 + mi * 16;
        #pragma unroll
        for (int nj = 0; nj < 8; nj++) {
            int cn = col0 + wn * 64 + nj * 8 + qid * 2;
            *reinterpret_cast<float2*>(&out[(long)(rbase + grp) * 1024 + cn]) =
                make_float2(acc[mi][nj][0], acc[mi][nj][1]);
            *reinterpret_cast<float2*>(&out[(long)(rbase + grp + 8) * 1024 + cn]) =
                make_float2(acc[mi][nj][2], acc[mi][nj][3]);
        }
    }
}

// ============================================================================
// Launch
// ============================================================================
extern "C" void kernel_launch(void* const* d_in, const int* in_sizes, int n_in,
                              void* d_out, int out_size) {
    const float* u  = (const float*)d_in[0];
    const float* w0 = (const float*)d_in[1];
    const float* b0 = (const float*)d_in[2];
    const float* w  = (const float*)d_in[3];
    const float* b  = (const float*)d_in[4];
    const float* wf = (const float*)d_in[5];
    const float* bf = (const float*)d_in[6];
    const float* xi = (const float*)d_in[7];
    float* out = (float*)d_out;

    void* p;
    cudaGetSymbolAddress(&p, g_uThi);  __nv_bfloat16* uThi = (__nv_bfloat16*)p;
    cudaGetSymbolAddress(&p, g_uTlo);  __nv_bfloat16* uTlo = (__nv_bfloat16*)p;
    cudaGetSymbolAddress(&p, g_W0hi);  __nv_bfloat16* W0hi = (__nv_bfloat16*)p;
    cudaGetSymbolAddress(&p, g_W0lo);  __nv_bfloat16* W0lo = (__nv_bfloat16*)p;
    cudaGetSymbolAddress(&p, g_Whi);   __nv_bfloat16* Whi  = (__nv_bfloat16*)p;
    cudaGetSymbolAddress(&p, g_Wlo);   __nv_bfloat16* Wlo  = (__nv_bfloat16*)p;
    cudaGetSymbolAddress(&p, g_Wfhi);  __nv_bfloat16* Wfhi = (__nv_bfloat16*)p;
    cudaGetSymbolAddress(&p, g_Wflo);  __nv_bfloat16* Wflo = (__nv_bfloat16*)p;
    cudaGetSymbolAddress(&p, g_actAhi); __nv_bfloat16* aAhi = (__nv_bfloat16*)p;
    cudaGetSymbolAddress(&p, g_actAlo); __nv_bfloat16* aAlo = (__nv_bfloat16*)p;
    cudaGetSymbolAddress(&p, g_actBhi); __nv_bfloat16* aBhi = (__nv_bfloat16*)p;
    cudaGetSymbolAddress(&p, g_actBlo); __nv_bfloat16* aBlo = (__nv_bfloat16*)p;
    cudaGetSymbolAddress(&p, g_Ah16);  __half* Ah16 = (__half*)p;
    cudaGetSymbolAddress(&p, g_Al16);  __half* Al16 = (__half*)p;
    cudaGetSymbolAddress(&p, g_G16);   __half* G16  = (__half*)p;

    cudaFuncSetAttribute(mlp_mma_kernel,
                         cudaFuncAttributeMaxDynamicSharedMemorySize, MLP_SMEM_TOTAL);
    cudaFuncSetAttribute(out_mma_kernel,
                         cudaFuncAttributeMaxDynamicSharedMemorySize, OUT_SMEM_TOTAL);

    // ---- precompute ----
    build_A16_kernel<<<4096, 256>>>(xi, Ah16, Al16);
    {
        long c0 = 64L * 256 * 64;
        split_kernel<<<(unsigned)((c0 + 1023) / 1024), 256>>>(w0, W0hi, W0lo, c0);
        long c1 = 3L * 64 * 256 * 256;
        split_kernel<<<(unsigned)((c1 + 1023) / 1024), 256>>>(w, Whi, Wlo, c1);
        long c2 = 64L * 65 * 256;
        split_kernel<<<(unsigned)((c2 + 1023) / 1024), 256>>>(wf, Wfhi, Wflo, c2);
    }
    transpose_u_split_kernel<<<dim3(32, 2), dim3(32, 32)>>>(u, uThi, uTlo);

    // ---- MLP chain (bf16 3-term, round-5 structure) ----
    mlp_mma_kernel<<<dim3(8, 2, 64), 256, MLP_SMEM_TOTAL>>>(
        W0hi, W0lo, 256L * 64, uThi, uTlo, 0L, b0, 256,
        aAhi, aAlo, 256L * 1024, 256, 64, 0);

    const __nv_bfloat16* sh = aAhi; const __nv_bfloat16* sl = aAlo;
    __nv_bfloat16* dh = aBhi; __nv_bfloat16* dl = aBlo;
    for (int i = 0; i < 3; i++) {
        mlp_mma_kernel<<<dim3(8, 2, 64), 256, MLP_SMEM_TOTAL>>>(
            Whi + (long)i * 64 * 256 * 256, Wlo + (long)i * 64 * 256 * 256,
            256L * 256, sh, sl, 256L * 1024,
            b + (long)i * 64 * 256, 256,
            dh, dl, 256L * 1024, 256, 256, 0);
        const __nv_bfloat16* th = sh; const __nv_bfloat16* tl = sl;
        sh = dh; sl = dl;
        dh = (__nv_bfloat16*)th; dl = (__nv_bfloat16*)tl;
    }

    // final layer: rows=65, mode 1 -> writes G directly as single fp16
    mlp_mma_kernel<<<dim3(8, 1, 64), 256, MLP_SMEM_TOTAL>>>(
        Wfhi, Wflo, 65L * 256, sh, sl, 256L * 1024, bf, 65,
        (__nv_bfloat16*)G16, nullptr, 65L * 1024, 65, 256, 1);

    // ---- output GEMM (fp16 2-term) ----
    out_mma_kernel<<<dim3(8, 32), 256, OUT_SMEM_TOTAL>>>(Ah16, Al16, G16, out);
}

// round 13
// speedup vs baseline: 2.4829x; 1.1434x over previous
#include <cuda_runtime.h>
#include <cuda_bf16.h>
#include <cuda_fp16.h>
#include <cstdint>

// ============================================================================
// spectralNNDeepshared2 — Round 11:
//   EVERYTHING on fp16 2-term mma.sync (confirmed HMMA-count ceiling):
//     MLP: W = exact fp16 hi/lo digits, X = single fp16, sigmoid epilogue
//          writes single-fp16 activations (G is just the last activation).
//     out-GEMM: A = exact fp16 hi/lo digits of xi-window, B = G single fp16
//               (unchanged from round 8, measured good).
// ============================================================================

// ---------------- scratch ----------------
__device__ __half g_uT16[64 * 1024];
__device__ __half g_W0hi[64 * 256 * 64];
__device__ __half g_W0lo[64 * 256 * 64];
__device__ __half g_Whi[3L * 64 * 256 * 256];
__device__ __half g_Wlo[3L * 64 * 256 * 256];
__device__ __half g_Wfhi[64 * 65 * 256];
__device__ __half g_Wflo[64 * 65 * 256];
__device__ __half g_actA16[64L * 256 * 1024];
__device__ __half g_actB16[64L * 256 * 1024];
__device__ __half g_Ah16[4096L * 4160];
__device__ __half g_Al16[4096L * 4160];
__device__ __half g_G16[4160L * 1024];

__device__ __forceinline__ float sigmoidf_fast(float x) {
    return 1.0f / (1.0f + __expf(-x));
}
__device__ __forceinline__ uint32_t smem_u32(const void* p) {
    uint32_t a;
    asm("{ .reg .u64 t; cvta.to.shared.u64 t, %1; cvt.u32.u64 %0, t; }"
        : "=r"(a) : "l"(p));
    return a;
}

// ---------------- cp.async / ldmatrix / mma helpers ----------------
__device__ __forceinline__ void cp16(uint32_t dst, const void* src) {
    asm volatile("cp.async.cg.shared.global [%0], [%1], 16;\n"
                 :: "r"(dst), "l"(src));
}
__device__ __forceinline__ void cp16z(uint32_t dst, const void* src, bool valid) {
    int sz = valid ? 16 : 0;
    asm volatile("cp.async.cg.shared.global [%0], [%1], 16, %2;\n"
                 :: "r"(dst), "l"(src), "r"(sz));
}
#define CP_COMMIT() asm volatile("cp.async.commit_group;\n" ::: "memory")
#define CP_WAIT(n)  asm volatile("cp.async.wait_group %0;\n" :: "n"(n) : "memory")

__device__ __forceinline__ void ldsm_x4(uint32_t* r, uint32_t addr) {
    asm volatile("ldmatrix.sync.aligned.m8n8.x4.shared.b16 {%0,%1,%2,%3}, [%4];"
        : "=r"(r[0]), "=r"(r[1]), "=r"(r[2]), "=r"(r[3]) : "r"(addr));
}
__device__ __forceinline__ void ldsm_x4t(uint32_t* r, uint32_t addr) {
    asm volatile("ldmatrix.sync.aligned.m8n8.x4.trans.shared.b16 {%0,%1,%2,%3}, [%4];"
        : "=r"(r[0]), "=r"(r[1]), "=r"(r[2]), "=r"(r[3]) : "r"(addr));
}
__device__ __forceinline__ void mma_f16(float* d, const uint32_t* a, const uint32_t* b) {
    asm volatile(
        "mma.sync.aligned.m16n8k16.row.col.f32.f16.f16.f32 "
        "{%0,%1,%2,%3}, {%4,%5,%6,%7}, {%8,%9}, {%0,%1,%2,%3};"
        : "+f"(d[0]), "+f"(d[1]), "+f"(d[2]), "+f"(d[3])
        : "r"(a[0]), "r"(a[1]), "r"(a[2]), "r"(a[3]), "r"(b[0]), "r"(b[1]));
}

// ============================================================================
// Precompute kernels
// ============================================================================
// fp32 -> exact fp16 hi/lo digit split
__global__ void split16_kernel(const float* __restrict__ src,
                               __half* __restrict__ hi,
                               __half* __restrict__ lo, long count)
{
    long i = (long)blockIdx.x * 1024 + threadIdx.x * 4;
    if (i + 3 >= count) {
        for (long k = i; k < count; k++) {
            float v = src[k];
            __half h = __float2half_rn(v);
            hi[k] = h;
            lo[k] = __float2half_rn(v - __half2float(h));
        }
        return;
    }
    float4 v4 = *reinterpret_cast<const float4*>(src + i);
    float vs[4] = {v4.x, v4.y, v4.z, v4.w};
    __half h4[4], l4[4];
    #pragma unroll
    for (int j = 0; j < 4; j++) {
        h4[j] = __float2half_rn(vs[j]);
        l4[j] = __float2half_rn(vs[j] - __half2float(h4[j]));
    }
    *reinterpret_cast<uint2*>(hi + i) = *reinterpret_cast<uint2*>(h4);
    *reinterpret_cast<uint2*>(lo + i) = *reinterpret_cast<uint2*>(l4);
}

// Transpose u (1024x64) -> uT (64x1024) single fp16
__global__ void transpose_u16_kernel(const float* __restrict__ u,
                                     __half* __restrict__ uT)
{
    __shared__ float t[32][33];
    int b0 = blockIdx.x * 32;
    int d0 = blockIdx.y * 32;
    int x = threadIdx.x, y = threadIdx.y;
    t[y][x] = u[(long)(b0 + y) * 64 + (d0 + x)];
    __syncthreads();
    uT[(long)(d0 + y) * 1024 + (b0 + x)] = __float2half_rn(t[x][y]);
}

// Sliding-window A (4096 x 4160) as exact fp16 hi/lo digits
__global__ void build_A16_kernel(const float* __restrict__ xi,
                                 __half* __restrict__ Ah,
                                 __half* __restrict__ Al)
{
    int n = blockIdx.x;
    for (int k = threadIdx.x; k < 4160; k += 256) {
        int m = k / 65;
        int j = k - m * 65;
        float v = xi[m * 4160 + n + j];
        __half h = __float2half_rn(v);
        Ah[(long)n * 4160 + k] = h;
        Al[(long)n * 4160 + k] = __float2half_rn(v - __half2float(h));
    }
}

// ============================================================================
// Shared smem layout: A (2-digit, 128x32) + B (single, 32x128), 3-stage ring
// ============================================================================
#define ASTRIDE 80
#define BSTRIDE 272
#define A_TILE  (128 * ASTRIDE)             // 10240
#define B_TILE  (32 * BSTRIDE)              // 8704
#define STAGE   (2 * A_TILE + B_TILE)       // 29184
#define NSTAGES 3
#define SMEM_TOTAL (NSTAGES * STAGE)        // 87552 (2 CTAs/SM fits)
#define O_AH 0
#define O_AL A_TILE
#define O_B  (2 * A_TILE)

// ============================================================================
// MLP layer: Y[m] = sigmoid(W[m] (rows x K) @ X[m] (K x 1024) + bias[m])
// fp16 2-term (W digits exact, X single). Writes single-fp16 activations.
// ============================================================================
__global__ __launch_bounds__(256, 2) void mlp_mma_kernel(
    const __half* __restrict__ Whi, const __half* __restrict__ Wlo,
    long wStride,
    const __half* __restrict__ X, long xStride,
    const float* __restrict__ bias_all, int biasStride,
    __half* __restrict__ Y, long yStride,
    int rows, int K)
{
    extern __shared__ char smem[];
    const uint32_t sb = smem_u32(smem);
    const int tid = threadIdx.x;
    const int lane = tid & 31;
    const int wid = tid >> 5;
    const int wm = wid & 3;
    const int wn = wid >> 2;
    const int m = blockIdx.z;
    const int row0 = blockIdx.y * 128;
    const int col0 = blockIdx.x * 128;

    const __half* Ah = Whi + (long)m * wStride;
    const __half* Al = Wlo + (long)m * wStride;
    const __half* Bx = X + (long)m * xStride;
    const float* bias = bias_all + (long)m * biasStride;

    float acc[2][8][4];
    #pragma unroll
    for (int mi = 0; mi < 2; mi++)
        #pragma unroll
        for (int nj = 0; nj < 8; nj++)
            #pragma unroll
            for (int q = 0; q < 4; q++) acc[mi][nj][q] = 0.0f;

    const int quad = lane >> 3;
    const int r8 = lane & 7;
    const uint32_t aoff = (wm * 32 + (quad & 1) * 8 + r8) * ASTRIDE + (quad >> 1) * 16;
    const uint32_t boff = ((quad & 1) * 8 + r8) * BSTRIDE + (wn * 64 + (quad >> 1) * 8) * 2;

    const int nChunks = K >> 5;

    auto load = [&](int stageIdx, int k0) {
        uint32_t sbase = sb + (uint32_t)stageIdx * STAGE;
        #pragma unroll
        for (int i = 0; i < 2; i++) {
            int idx = tid + i * 256;
            int r = idx >> 2;
            int c = idx & 3;
            int gr = row0 + r;
            bool ok = gr < rows;
            long g = (long)(ok ? gr : 0) * K + k0 + c * 8;
            uint32_t d = r * ASTRIDE + c * 16;
            cp16z(sbase + O_AH + d, Ah + g, ok);
            cp16z(sbase + O_AL + d, Al + g, ok);
        }
        #pragma unroll
        for (int i = 0; i < 2; i++) {
            int idx = tid + i * 256;
            int r = idx >> 4;
            int c = idx & 15;
            long g = (long)(k0 + r) * 1024 + col0 + c * 8;
            cp16(sbase + O_B + r * BSTRIDE + c * 16, Bx + g);
        }
    };

    load(0, 0);
    CP_COMMIT();
    if (nChunks > 1) load(1, 32);
    CP_COMMIT();

    int curStage = 0, nxtStage = 2;
    for (int t = 0; t < nChunks; t++) {
        CP_WAIT(1);
        __syncthreads();
        if (t + 2 < nChunks) load(nxtStage, (t + 2) * 32);
        CP_COMMIT();

        const uint32_t cur = sb + (uint32_t)curStage * STAGE;
        curStage = (curStage == NSTAGES - 1) ? 0 : curStage + 1;
        nxtStage = (nxtStage == NSTAGES - 1) ? 0 : nxtStage + 1;

        #pragma unroll
        for (int ks = 0; ks < 2; ks++) {
            uint32_t ah[2][4], al[2][4];
            ldsm_x4(ah[0], cur + O_AH + aoff + ks * 32);
            ldsm_x4(ah[1], cur + O_AH + aoff + 16 * ASTRIDE + ks * 32);
            ldsm_x4(al[0], cur + O_AL + aoff + ks * 32);
            ldsm_x4(al[1], cur + O_AL + aoff + 16 * ASTRIDE + ks * 32);

            #pragma unroll
            for (int g = 0; g < 4; g++) {
                uint32_t rh[4];
                ldsm_x4t(rh, cur + O_B + boff + g * 32 + ks * 16 * BSTRIDE);
                mma_f16(acc[0][2 * g],     ah[0], &rh[0]);
                mma_f16(acc[0][2 * g + 1], ah[0], &rh[2]);
                mma_f16(acc[1][2 * g],     ah[1], &rh[0]);
                mma_f16(acc[1][2 * g + 1], ah[1], &rh[2]);
                mma_f16(acc[0][2 * g],     al[0], &rh[0]);
                mma_f16(acc[0][2 * g + 1], al[0], &rh[2]);
                mma_f16(acc[1][2 * g],     al[1], &rh[0]);
                mma_f16(acc[1][2 * g + 1], al[1], &rh[2]);
            }
        }
        __syncthreads();
    }

    // epilogue: bias + sigmoid -> single fp16
    const int grp = lane >> 2;
    const int qid = lane & 3;
    __half* y = Y + (long)m * yStride;
    #pragma unroll
    for (int mi = 0; mi < 2; mi++) {
        int rbase = row0 + wm * 32 + mi * 16;
        #pragma unroll
        for (int half = 0; half < 2; half++) {
            int gr = rbase + grp + half * 8;
            if (gr >= rows) continue;
            float bv = bias[gr];
            #pragma unroll
            for (int nj = 0; nj < 8; nj++) {
                int cn = col0 + wn * 64 + nj * 8 + qid * 2;
                float y0 = sigmoidf_fast(acc[mi][nj][2 * half + 0] + bv);
                float y1 = sigmoidf_fast(acc[mi][nj][2 * half + 1] + bv);
                __half2 hp;
                hp.x = __float2half_rn(y0);
                hp.y = __float2half_rn(y1);
                *reinterpret_cast<__half2*>(y + (long)gr * 1024 + cn) = hp;
            }
        }
    }
}

// ============================================================================
// Output GEMM, fp16 2-term (round-8, measured good):
//   out(4096x1024) = A(4096x4160) @ G(4160x1024)
// ============================================================================
__global__ __launch_bounds__(256, 2) void out_mma_kernel(
    const __half* __restrict__ Ahi, const __half* __restrict__ Alo,
    const __half* __restrict__ Bg,
    float* __restrict__ out)
{
    extern __shared__ char smem[];
    const uint32_t sb = smem_u32(smem);
    const int tid = threadIdx.x;
    const int lane = tid & 31;
    const int wid = tid >> 5;
    const int wm = wid & 3;
    const int wn = wid >> 2;
    const int n0 = blockIdx.y * 128;
    const int col0 = blockIdx.x * 128;

    float acc[2][8][4];
    #pragma unroll
    for (int mi = 0; mi < 2; mi++)
        #pragma unroll
        for (int nj = 0; nj < 8; nj++)
            #pragma unroll
            for (int q = 0; q < 4; q++) acc[mi][nj][q] = 0.0f;

    const int quad = lane >> 3;
    const int r8 = lane & 7;
    const uint32_t aoff = (wm * 32 + (quad & 1) * 8 + r8) * ASTRIDE + (quad >> 1) * 16;
    const uint32_t boff = ((quad & 1) * 8 + r8) * BSTRIDE + (wn * 64 + (quad >> 1) * 8) * 2;

    auto load = [&](int stageIdx, int k0) {
        uint32_t sbase = sb + (uint32_t)stageIdx * STAGE;
        #pragma unroll
        for (int i = 0; i < 2; i++) {
            int idx = tid + i * 256;
            int r = idx >> 2;
            int c = idx & 3;
            long g = (long)(n0 + r) * 4160 + k0 + c * 8;
            uint32_t d = r * ASTRIDE + c * 16;
            cp16(sbase + O_AH + d, Ahi + g);
            cp16(sbase + O_AL + d, Alo + g);
        }
        #pragma unroll
        for (int i = 0; i < 2; i++) {
            int idx = tid + i * 256;
            int r = idx >> 4;
            int c = idx & 15;
            long g = (long)(k0 + r) * 1024 + col0 + c * 8;
            cp16(sbase + O_B + r * BSTRIDE + c * 16, Bg + g);
        }
    };

    load(0, 0);
    CP_COMMIT();
    load(1, 32);
    CP_COMMIT();

    int curStage = 0, nxtStage = 2;
    for (int t = 0; t < 130; t++) {
        CP_WAIT(1);
        __syncthreads();
        if (t + 2 < 130) load(nxtStage, (t + 2) * 32);
        CP_COMMIT();

        const uint32_t cur = sb + (uint32_t)curStage * STAGE;
        curStage = (curStage == NSTAGES - 1) ? 0 : curStage + 1;
        nxtStage = (nxtStage == NSTAGES - 1) ? 0 : nxtStage + 1;

        #pragma unroll
        for (int ks = 0; ks < 2; ks++) {
            uint32_t ah[2][4], al[2][4];
            ldsm_x4(ah[0], cur + O_AH + aoff + ks * 32);
            ldsm_x4(ah[1], cur + O_AH + aoff + 16 * ASTRIDE + ks * 32);
            ldsm_x4(al[0], cur + O_AL + aoff + ks * 32);
            ldsm_x4(al[1], cur + O_AL + aoff + 16 * ASTRIDE + ks * 32);

            #pragma unroll
            for (int g = 0; g < 4; g++) {
                uint32_t rh[4];
                ldsm_x4t(rh, cur + O_B + boff + g * 32 + ks * 16 * BSTRIDE);
                mma_f16(acc[0][2 * g],     ah[0], &rh[0]);
                mma_f16(acc[0][2 * g + 1], ah[0], &rh[2]);
                mma_f16(acc[1][2 * g],     ah[1], &rh[0]);
                mma_f16(acc[1][2 * g + 1], ah[1], &rh[2]);
                mma_f16(acc[0][2 * g],     al[0], &rh[0]);
                mma_f16(acc[0][2 * g + 1], al[0], &rh[2]);
                mma_f16(acc[1][2 * g],     al[1], &rh[0]);
                mma_f16(acc[1][2 * g + 1], al[1], &rh[2]);
            }
        }
        __syncthreads();
    }

    const int grp = lane >> 2;
    const int qid = lane & 3;
    #pragma unroll
    for (int mi = 0; mi < 2; mi++) {
        int rbase = n0 + wm * 32 + mi * 16;
        #pragma unroll
        for (int nj = 0; nj < 8; nj++) {
            int cn = col0 + wn * 64 + nj * 8 + qid * 2;
            *reinterpret_cast<float2*>(&out[(long)(rbase + grp) * 1024 + cn]) =
                make_float2(acc[mi][nj][0], acc[mi][nj][1]);
            *reinterpret_cast<float2*>(&out[(long)(rbase + grp + 8) * 1024 + cn]) =
                make_float2(acc[mi][nj][2], acc[mi][nj][3]);
        }
    }
}

// ============================================================================
// Launch
// ============================================================================
extern "C" void kernel_launch(void* const* d_in, const int* in_sizes, int n_in,
                              void* d_out, int out_size) {
    const float* u  = (const float*)d_in[0];
    const float* w0 = (const float*)d_in[1];
    const float* b0 = (const float*)d_in[2];
    const float* w  = (const float*)d_in[3];
    const float* b  = (const float*)d_in[4];
    const float* wf = (const float*)d_in[5];
    const float* bf = (const float*)d_in[6];
    const float* xi = (const float*)d_in[7];
    float* out = (float*)d_out;

    void* p;
    cudaGetSymbolAddress(&p, g_uT16);  __half* uT16 = (__half*)p;
    cudaGetSymbolAddress(&p, g_W0hi);  __half* W0hi = (__half*)p;
    cudaGetSymbolAddress(&p, g_W0lo);  __half* W0lo = (__half*)p;
    cudaGetSymbolAddress(&p, g_Whi);   __half* Whi  = (__half*)p;
    cudaGetSymbolAddress(&p, g_Wlo);   __half* Wlo  = (__half*)p;
    cudaGetSymbolAddress(&p, g_Wfhi);  __half* Wfhi = (__half*)p;
    cudaGetSymbolAddress(&p, g_Wflo);  __half* Wflo = (__half*)p;
    cudaGetSymbolAddress(&p, g_actA16); __half* actA = (__half*)p;
    cudaGetSymbolAddress(&p, g_actB16); __half* actB = (__half*)p;
    cudaGetSymbolAddress(&p, g_Ah16);  __half* Ah16 = (__half*)p;
    cudaGetSymbolAddress(&p, g_Al16);  __half* Al16 = (__half*)p;
    cudaGetSymbolAddress(&p, g_G16);   __half* G16  = (__half*)p;

    cudaFuncSetAttribute(mlp_mma_kernel,
                         cudaFuncAttributeMaxDynamicSharedMemorySize, SMEM_TOTAL);
    cudaFuncSetAttribute(out_mma_kernel,
                         cudaFuncAttributeMaxDynamicSharedMemorySize, SMEM_TOTAL);

    // ---- precompute ----
    build_A16_kernel<<<4096, 256>>>(xi, Ah16, Al16);
    {
        long c0 = 64L * 256 * 64;
        split16_kernel<<<(unsigned)((c0 + 1023) / 1024), 256>>>(w0, W0hi, W0lo, c0);
        long c1 = 3L * 64 * 256 * 256;
        split16_kernel<<<(unsigned)((c1 + 1023) / 1024), 256>>>(w, Whi, Wlo, c1);
        long c2 = 64L * 65 * 256;
        split16_kernel<<<(unsigned)((c2 + 1023) / 1024), 256>>>(wf, Wfhi, Wflo, c2);
    }
    transpose_u16_kernel<<<dim3(32, 2), dim3(32, 32)>>>(u, uT16);

    // ---- MLP chain (fp16 2-term) ----
    // layer 0: rows=256, K=64, X = uT (shared across m: xStride=0)
    mlp_mma_kernel<<<dim3(8, 2, 64), 256, SMEM_TOTAL>>>(
        W0hi, W0lo, 256L * 64, uT16, 0L, b0, 256,
        actA, 256L * 1024, 256, 64);

    const __half* src = actA;
    __half* dst = actB;
    for (int i = 0; i < 3; i++) {
        mlp_mma_kernel<<<dim3(8, 2, 64), 256, SMEM_TOTAL>>>(
            Whi + (long)i * 64 * 256 * 256, Wlo + (long)i * 64 * 256 * 256,
            256L * 256, src, 256L * 1024,
            b + (long)i * 64 * 256, 256,
            dst, 256L * 1024, 256, 256);
        const __half* t = src;
        src = dst;
        dst = (__half*)t;
    }

    // final layer: rows=65 -> G (4160 x 1024) single fp16
    mlp_mma_kernel<<<dim3(8, 1, 64), 256, SMEM_TOTAL>>>(
        Wfhi, Wflo, 65L * 256, src, 256L * 1024, bf, 65,
        G16, 65L * 1024, 65, 256);

    // ---- output GEMM (fp16 2-term) ----
    out_mma_kernel<<<dim3(8, 32), 256, SMEM_TOTAL>>>(Ah16, Al16, G16, out);
}